// round 1
// baseline (speedup 1.0000x reference)
#include <cuda_runtime.h>
#include <math.h>

#define NN 40000
#define EE 1280000
#define ETOT (EE + NN)
#define DD 256
#define BB 64
#define NCLS 20

// ---------------- scratch (static device allocations; no runtime alloc) ----
__device__ float g_x0[NN * DD];
__device__ float g_x1[NN * DD];
__device__ float g_h[NN * DD];
__device__ float g_agg[NN * DD];
__device__ float g_ssrc[NN * 8];
__device__ float g_sdst[NN * 8];
__device__ int   g_deg[NN];
__device__ int   g_off[NN + 1];
__device__ int   g_pos[NN];
__device__ int   g_csr[ETOT];
__device__ float g_p2[BB * DD];
__device__ float g_p0[BB * DD];
__device__ float g_cnt[BB];

// ---------------- GEMM: C[M,256] = A[M,K] @ B[K,256] (+bias), M%64==0, K%8==0
__global__ void __launch_bounds__(256, 2) gemm_kernel(
    const float* __restrict__ A, const float* __restrict__ B,
    const float* __restrict__ bias, float* __restrict__ C, int K)
{
    __shared__ float As[8][68];   // padded: conflict-free STS, 16B-aligned rows
    __shared__ float Bs[8][256];

    const int tid  = threadIdx.x;
    const int row0 = blockIdx.x * 64;

    const int a_r = tid >> 2;          // 0..63
    const int a_c = (tid & 3) * 2;     // 0,2,4,6
    const int b_r = tid >> 5;          // 0..7
    const int b_c = (tid & 31) * 8;    // 0..248
    const int tr  = (tid >> 5) * 8;    // 0..56
    const int tc  = (tid & 31) * 8;    // 0..248

    float acc[8][8];
#pragma unroll
    for (int i = 0; i < 8; i++)
#pragma unroll
        for (int j = 0; j < 8; j++) acc[i][j] = 0.f;

    const float* Ap = A + (row0 + a_r) * K + a_c;
    const float* Bp = B + b_r * 256 + b_c;

    for (int k0 = 0; k0 < K; k0 += 8) {
        float2 av  = *(const float2*)(Ap + k0);
        float4 bv0 = *(const float4*)(Bp + k0 * 256);
        float4 bv1 = *(const float4*)(Bp + k0 * 256 + 4);
        As[a_c][a_r]     = av.x;
        As[a_c + 1][a_r] = av.y;
        *(float4*)&Bs[b_r][b_c]     = bv0;
        *(float4*)&Bs[b_r][b_c + 4] = bv1;
        __syncthreads();
#pragma unroll
        for (int k = 0; k < 8; k++) {
            float4 a0 = *(const float4*)&As[k][tr];
            float4 a1 = *(const float4*)&As[k][tr + 4];
            float4 c0 = *(const float4*)&Bs[k][tc];
            float4 c1 = *(const float4*)&Bs[k][tc + 4];
            float ar[8] = {a0.x, a0.y, a0.z, a0.w, a1.x, a1.y, a1.z, a1.w};
            float br[8] = {c0.x, c0.y, c0.z, c0.w, c1.x, c1.y, c1.z, c1.w};
#pragma unroll
            for (int i = 0; i < 8; i++)
#pragma unroll
                for (int j = 0; j < 8; j++)
                    acc[i][j] += ar[i] * br[j];
        }
        __syncthreads();
    }

    float bb[8];
#pragma unroll
    for (int j = 0; j < 8; j++) bb[j] = bias ? bias[tc + j] : 0.f;

#pragma unroll
    for (int i = 0; i < 8; i++) {
        int row = row0 + tr + i;
        float4 o0 = make_float4(acc[i][0] + bb[0], acc[i][1] + bb[1],
                                acc[i][2] + bb[2], acc[i][3] + bb[3]);
        float4 o1 = make_float4(acc[i][4] + bb[4], acc[i][5] + bb[5],
                                acc[i][6] + bb[6], acc[i][7] + bb[7]);
        *(float4*)(C + row * 256 + tc)     = o0;
        *(float4*)(C + row * 256 + tc + 4) = o1;
    }
}

// ---------------- CSR build ------------------------------------------------
__global__ void deg_init_kernel(int* deg) {
    int i = blockIdx.x * blockDim.x + threadIdx.x;
    if (i < NN) deg[i] = 1;  // self-loop
}

__global__ void deg_count_kernel(const int* __restrict__ ei, int* deg) {
    int i = blockIdx.x * blockDim.x + threadIdx.x;
    if (i < EE) atomicAdd(&deg[ei[EE + i]], 1);
}

__global__ void scan_kernel(const int* __restrict__ deg, int* off, int* pos) {
    __shared__ int sm[1024];
    const int t = threadIdx.x;
    const int base = t * 40;
    int v[40];
    int local = 0;
#pragma unroll
    for (int i = 0; i < 40; i++) {
        int idx = base + i;
        int d = (idx < NN) ? deg[idx] : 0;
        v[i] = local;
        local += d;
    }
    sm[t] = local;
    __syncthreads();
    for (int o = 1; o < 1024; o <<= 1) {
        int add = (t >= o) ? sm[t - o] : 0;
        __syncthreads();
        sm[t] += add;
        __syncthreads();
    }
    int excl = sm[t] - local;
#pragma unroll
    for (int i = 0; i < 40; i++) {
        int idx = base + i;
        if (idx < NN) {
            int o_ = excl + v[i];
            off[idx] = o_;
            pos[idx] = o_;
        }
    }
    if (t == 1023) off[NN] = sm[1023];
}

__global__ void csr_fill_kernel(const int* __restrict__ ei, int* pos, int* csr) {
    int i = blockIdx.x * blockDim.x + threadIdx.x;
    if (i >= ETOT) return;
    int s, d;
    if (i < EE) { s = ei[i]; d = ei[EE + i]; }
    else        { s = d = i - EE; }
    int p = atomicAdd(&pos[d], 1);
    csr[p] = s;
}

// ---------------- attention scores ----------------------------------------
template <int H, int C>
__global__ void scores_kernel(const float* __restrict__ h,
                              const float* __restrict__ asrc,
                              const float* __restrict__ adst,
                              float* __restrict__ ssrc, float* __restrict__ sdst)
{
    int gw = (blockIdx.x * blockDim.x + threadIdx.x) >> 5;
    if (gw >= NN) return;
    int lane = threadIdx.x & 31;

    const float4* hp = (const float4*)(h + gw * 256 + lane * 8);
    float4 v0 = hp[0], v1 = hp[1];
    const float4* ap = (const float4*)(asrc + lane * 8);
    float4 a0 = ap[0], a1 = ap[1];
    const float4* dp = (const float4*)(adst + lane * 8);
    float4 d0 = dp[0], d1 = dp[1];

    float ps = v0.x * a0.x + v0.y * a0.y + v0.z * a0.z + v0.w * a0.w +
               v1.x * a1.x + v1.y * a1.y + v1.z * a1.z + v1.w * a1.w;
    float pd = v0.x * d0.x + v0.y * d0.y + v0.z * d0.z + v0.w * d0.w +
               v1.x * d1.x + v1.y * d1.y + v1.z * d1.z + v1.w * d1.w;

    const int GC = C / 8;  // lanes per head
#pragma unroll
    for (int o = 1; o < GC; o <<= 1) {
        ps += __shfl_xor_sync(0xffffffffu, ps, o);
        pd += __shfl_xor_sync(0xffffffffu, pd, o);
    }
    int myh = lane / GC;
    if ((lane & (GC - 1)) == 0) {
        ssrc[gw * H + myh] = ps;
        sdst[gw * H + myh] = pd;
    }
}

// ---------------- GAT aggregation: one warp per destination ---------------
template <int H, int C>
__global__ void agg_kernel(const float* __restrict__ ssrc,
                           const float* __restrict__ sdst,
                           const float* __restrict__ h,
                           const int* __restrict__ off,
                           const int* __restrict__ csr,
                           float* __restrict__ out)
{
    int gw = (blockIdx.x * blockDim.x + threadIdx.x) >> 5;
    if (gw >= NN) return;
    int lane = threadIdx.x & 31;

    int e0 = off[gw];
    int deg = off[gw + 1] - e0;

    const int ES = 32 / H;
    int hh = lane % H;
    int j0 = lane / H;

    float sd = __ldg(&sdst[gw * H + hh]);
    float m = -1e30f;
    for (int j = j0; j < deg; j += ES) {
        int s = __ldg(&csr[e0 + j]);
        float e = __ldg(&ssrc[s * H + hh]) + sd;
        e = e > 0.f ? e : 0.2f * e;
        m = fmaxf(m, e);
    }
#pragma unroll
    for (int o = H; o < 32; o <<= 1) m = fmaxf(m, __shfl_xor_sync(0xffffffffu, m, o));

    float z = 0.f;
    for (int j = j0; j < deg; j += ES) {
        int s = __ldg(&csr[e0 + j]);
        float e = __ldg(&ssrc[s * H + hh]) + sd;
        e = e > 0.f ? e : 0.2f * e;
        z += __expf(e - m);
    }
#pragma unroll
    for (int o = H; o < 32; o <<= 1) z += __shfl_xor_sync(0xffffffffu, z, o);

    // pass 3: lane owns cols [lane*8, lane*8+8) -> exactly one head
    const int myh = (lane * 8) / C;
    float my_m  = __shfl_sync(0xffffffffu, m, myh);
    float my_zi = 1.f / __shfl_sync(0xffffffffu, z, myh);
    float my_sd = __ldg(&sdst[gw * H + myh]);

    float acc[8] = {0.f, 0.f, 0.f, 0.f, 0.f, 0.f, 0.f, 0.f};
    for (int j = 0; j < deg; j++) {
        int s = __ldg(&csr[e0 + j]);
        float e = __ldg(&ssrc[s * H + myh]) + my_sd;
        e = e > 0.f ? e : 0.2f * e;
        float a = __expf(e - my_m) * my_zi;
        const float4* hp = (const float4*)(h + s * 256 + lane * 8);
        float4 v0 = __ldg(hp);
        float4 v1 = __ldg(hp + 1);
        acc[0] += a * v0.x; acc[1] += a * v0.y; acc[2] += a * v0.z; acc[3] += a * v0.w;
        acc[4] += a * v1.x; acc[5] += a * v1.y; acc[6] += a * v1.z; acc[7] += a * v1.w;
    }
    float4* op = (float4*)(out + gw * 256 + lane * 8);
    op[0] = make_float4(acc[0], acc[1], acc[2], acc[3]);
    op[1] = make_float4(acc[4], acc[5], acc[6], acc[7]);
}

// ---------------- elu + bias + residual + layernorm (warp per row) --------
__global__ void post_kernel(const float* __restrict__ agg,
                            const float* __restrict__ bias,
                            const float* __restrict__ xin,
                            const float* __restrict__ g,
                            const float* __restrict__ be,
                            float* __restrict__ xout)
{
    int gw = (blockIdx.x * blockDim.x + threadIdx.x) >> 5;
    if (gw >= NN) return;
    int lane = threadIdx.x & 31;
    int base = gw * 256 + lane * 8;

    float4 a0 = *(const float4*)(agg + base);
    float4 a1 = *(const float4*)(agg + base + 4);
    float4 b0 = *(const float4*)(bias + lane * 8);
    float4 b1 = *(const float4*)(bias + lane * 8 + 4);
    float4 x0 = *(const float4*)(xin + base);
    float4 x1 = *(const float4*)(xin + base + 4);

    float av[8] = {a0.x + b0.x, a0.y + b0.y, a0.z + b0.z, a0.w + b0.w,
                   a1.x + b1.x, a1.y + b1.y, a1.z + b1.z, a1.w + b1.w};
    float xv[8] = {x0.x, x0.y, x0.z, x0.w, x1.x, x1.y, x1.z, x1.w};

    float v[8];
    float sum = 0.f, sq = 0.f;
#pragma unroll
    for (int k = 0; k < 8; k++) {
        float t = av[k];
        t = (t > 0.f) ? t : (__expf(t) - 1.f);   // elu
        t += xv[k];                               // residual
        v[k] = t;
        sum += t;
        sq += t * t;
    }
#pragma unroll
    for (int o = 1; o < 32; o <<= 1) {
        sum += __shfl_xor_sync(0xffffffffu, sum, o);
        sq  += __shfl_xor_sync(0xffffffffu, sq, o);
    }
    float mean = sum * (1.f / 256.f);
    float var  = sq * (1.f / 256.f) - mean * mean;
    float rs   = rsqrtf(var + 1e-5f);

    float4 g0 = *(const float4*)(g + lane * 8);
    float4 g1 = *(const float4*)(g + lane * 8 + 4);
    float4 e0 = *(const float4*)(be + lane * 8);
    float4 e1 = *(const float4*)(be + lane * 8 + 4);
    float gv[8] = {g0.x, g0.y, g0.z, g0.w, g1.x, g1.y, g1.z, g1.w};
    float ev[8] = {e0.x, e0.y, e0.z, e0.w, e1.x, e1.y, e1.z, e1.w};

    float o0[8];
#pragma unroll
    for (int k = 0; k < 8; k++) o0[k] = (v[k] - mean) * rs * gv[k] + ev[k];
    *(float4*)(xout + base)     = make_float4(o0[0], o0[1], o0[2], o0[3]);
    *(float4*)(xout + base + 4) = make_float4(o0[4], o0[5], o0[6], o0[7]);
}

// ---------------- pooling --------------------------------------------------
__global__ void pool_init_kernel(float* p2, float* p0, float* cnt) {
    int i = blockIdx.x * blockDim.x + threadIdx.x;
    if (i < BB * DD) { p2[i] = 0.f; p0[i] = 0.f; }
    if (i < BB) cnt[i] = 0.f;
}

__global__ void pool_acc_kernel(const float* __restrict__ x2,
                                const float* __restrict__ x0,
                                const int* __restrict__ batch,
                                float* p2, float* p0, float* cnt)
{
    int r = blockIdx.x;
    int t = threadIdx.x;
    int b = batch[r];
    atomicAdd(&p2[b * 256 + t], x2[r * 256 + t]);
    atomicAdd(&p0[b * 256 + t], x0[r * 256 + t]);
    if (t == 0) atomicAdd(&cnt[b], 1.f);
}

// ---------------- classification head (block per graph) -------------------
__global__ void head_kernel(const float* __restrict__ p2,
                            const float* __restrict__ p0,
                            const float* __restrict__ cnt,
                            const float* __restrict__ Wf,  const float* __restrict__ bf,
                            const float* __restrict__ Wc1, const float* __restrict__ bc1,
                            const float* __restrict__ Wc2, const float* __restrict__ bc2,
                            float* __restrict__ out)
{
    __shared__ float xc[512];
    __shared__ float f[256];
    __shared__ float c1[128];
    __shared__ float lg[20];

    int b = blockIdx.x, t = threadIdx.x;
    float c = fmaxf(cnt[b], 1.f);
    xc[t]       = p2[b * 256 + t] / c;
    xc[256 + t] = p0[b * 256 + t] / c;
    __syncthreads();

    float acc = bf[t];
    for (int i = 0; i < 512; i++) acc += xc[i] * Wf[i * 256 + t];
    f[t] = fmaxf(acc, 0.f);
    __syncthreads();

    if (t < 128) {
        float a = bc1[t];
        for (int i = 0; i < 256; i++) a += f[i] * Wc1[i * 128 + t];
        c1[t] = fmaxf(a, 0.f);
    }
    __syncthreads();

    if (t < 20) {
        float a = bc2[t];
        for (int i = 0; i < 128; i++) a += c1[i] * Wc2[i * 20 + t];
        lg[t] = a;
    }
    __syncthreads();

    if (t < 32) {
        float v = (t < 20) ? lg[t] : -1e30f;
        float m = v;
#pragma unroll
        for (int o = 1; o < 32; o <<= 1) m = fmaxf(m, __shfl_xor_sync(0xffffffffu, m, o));
        float e = (t < 20) ? expf(v - m) : 0.f;
        float s = e;
#pragma unroll
        for (int o = 1; o < 32; o <<= 1) s += __shfl_xor_sync(0xffffffffu, s, o);
        if (t < 20) out[b * 20 + t] = v - m - logf(s);
    }
}

// ---------------- launcher -------------------------------------------------
extern "C" void kernel_launch(void* const* d_in, const int* in_sizes, int n_in,
                              void* d_out, int out_size)
{
    const float* x    = (const float*)d_in[0];
    const int*   ei   = (const int*)  d_in[1];
    const int*   batch= (const int*)  d_in[2];
    const float* W_in = (const float*)d_in[3];
    const float* b_in = (const float*)d_in[4];
    const float* W1   = (const float*)d_in[5];
    const float* as1  = (const float*)d_in[6];
    const float* ad1  = (const float*)d_in[7];
    const float* b1   = (const float*)d_in[8];
    const float* g1   = (const float*)d_in[9];
    const float* be1  = (const float*)d_in[10];
    const float* W2   = (const float*)d_in[11];
    const float* as2  = (const float*)d_in[12];
    const float* ad2  = (const float*)d_in[13];
    const float* b2   = (const float*)d_in[14];
    const float* g2   = (const float*)d_in[15];
    const float* be2  = (const float*)d_in[16];
    const float* Wf   = (const float*)d_in[17];
    const float* bfv  = (const float*)d_in[18];
    const float* Wc1  = (const float*)d_in[19];
    const float* bc1  = (const float*)d_in[20];
    const float* Wc2  = (const float*)d_in[21];
    const float* bc2  = (const float*)d_in[22];
    float* out = (float*)d_out;

    float *x0, *x1, *h, *agg, *ssrc, *sdst, *p2, *p0, *cnt;
    int *deg, *off, *pos, *csr;
    cudaGetSymbolAddress((void**)&x0,  g_x0);
    cudaGetSymbolAddress((void**)&x1,  g_x1);
    cudaGetSymbolAddress((void**)&h,   g_h);
    cudaGetSymbolAddress((void**)&agg, g_agg);
    cudaGetSymbolAddress((void**)&ssrc,g_ssrc);
    cudaGetSymbolAddress((void**)&sdst,g_sdst);
    cudaGetSymbolAddress((void**)&deg, g_deg);
    cudaGetSymbolAddress((void**)&off, g_off);
    cudaGetSymbolAddress((void**)&pos, g_pos);
    cudaGetSymbolAddress((void**)&csr, g_csr);
    cudaGetSymbolAddress((void**)&p2,  g_p2);
    cudaGetSymbolAddress((void**)&p0,  g_p0);
    cudaGetSymbolAddress((void**)&cnt, g_cnt);

    const int WARP_BLOCKS = NN / 8;           // 5000 blocks of 8 warps

    // CSR build
    deg_init_kernel<<<(NN + 255) / 256, 256>>>(deg);
    deg_count_kernel<<<(EE + 255) / 256, 256>>>(ei, deg);
    scan_kernel<<<1, 1024>>>(deg, off, pos);
    csr_fill_kernel<<<(ETOT + 255) / 256, 256>>>(ei, pos, csr);

    // input projection
    gemm_kernel<<<NN / 64, 256>>>(x, W_in, b_in, x0, 5000);

    // conv1
    gemm_kernel<<<NN / 64, 256>>>(x0, W1, nullptr, h, 256);
    scores_kernel<8, 32><<<WARP_BLOCKS, 256>>>(h, as1, ad1, ssrc, sdst);
    agg_kernel<8, 32><<<WARP_BLOCKS, 256>>>(ssrc, sdst, h, off, csr, agg);
    post_kernel<<<WARP_BLOCKS, 256>>>(agg, b1, x0, g1, be1, x1);

    // conv2
    gemm_kernel<<<NN / 64, 256>>>(x1, W2, nullptr, h, 256);
    scores_kernel<4, 64><<<WARP_BLOCKS, 256>>>(h, as2, ad2, ssrc, sdst);
    agg_kernel<4, 64><<<WARP_BLOCKS, 256>>>(ssrc, sdst, h, off, csr, agg);
    post_kernel<<<WARP_BLOCKS, 256>>>(agg, b2, x1, g2, be2, h);  // h := x2

    // pooling + head
    pool_init_kernel<<<64, 256>>>(p2, p0, cnt);
    pool_acc_kernel<<<NN, 256>>>(h, x0, batch, p2, p0, cnt);
    head_kernel<<<BB, 256>>>(p2, p0, cnt, Wf, bfv, Wc1, bc1, Wc2, bc2, out);
}

// round 3
// speedup vs baseline: 1.9944x; 1.9944x over previous
#include <cuda_runtime.h>
#include <cuda_bf16.h>
#include <math.h>
#include <cstdint>

#define NN 40000
#define EE 1280000
#define ETOT (EE + NN)
#define DD 256
#define BB 64
#define NCLS 20
#define KBIG 5000
#define KPBIG 5024   /* 157 * 32 */

// ---------------- scratch (static device allocations) ----------------------
__device__ float g_x0[NN * DD];
__device__ float g_x1[NN * DD];
__device__ float g_h[NN * DD];
__device__ float g_agg[NN * DD];
__device__ float g_ssrc[NN * 8];
__device__ float g_sdst[NN * 8];
__device__ int   g_deg[NN];
__device__ int   g_off[NN + 1];
__device__ int   g_pos[NN];
__device__ int   g_csr[ETOT];
__device__ float g_p2[BB * DD];
__device__ float g_p0[BB * DD];
__device__ float g_cnt[BB];
__device__ __nv_bfloat16 g_wbt_hi[256 * KPBIG];
__device__ __nv_bfloat16 g_wbt_lo[256 * KPBIG];
__device__ __nv_bfloat16 g_w1t_hi[256 * 256];
__device__ __nv_bfloat16 g_w1t_lo[256 * 256];
__device__ __nv_bfloat16 g_w2t_hi[256 * 256];
__device__ __nv_bfloat16 g_w2t_lo[256 * 256];

__device__ __forceinline__ uint32_t bf2pack(float a, float b) {
    __nv_bfloat162 t;
    t.x = __float2bfloat16(a);
    t.y = __float2bfloat16(b);
    return *reinterpret_cast<uint32_t*>(&t);
}

__device__ __forceinline__ void mma16816(float* c, const uint32_t* a, const uint32_t* b) {
    asm volatile(
        "mma.sync.aligned.m16n8k16.row.col.f32.bf16.bf16.f32 "
        "{%0,%1,%2,%3}, {%4,%5,%6,%7}, {%8,%9}, {%0,%1,%2,%3};"
        : "+f"(c[0]), "+f"(c[1]), "+f"(c[2]), "+f"(c[3])
        : "r"(a[0]), "r"(a[1]), "r"(a[2]), "r"(a[3]), "r"(b[0]), "r"(b[1]));
}

// ---------------- weight prep: W[K,256] -> Wt[256,KP] hi/lo, zero-padded ----
__global__ void wprep_kernel(const float* __restrict__ W,
                             __nv_bfloat16* __restrict__ th,
                             __nv_bfloat16* __restrict__ tl, int K, int KP)
{
    int i = blockIdx.x * 256 + threadIdx.x;
    if (i >= 256 * KP) return;
    int n = i / KP, k = i % KP;
    float v = (k < K) ? __ldg(&W[k * 256 + n]) : 0.f;
    __nv_bfloat16 h = __float2bfloat16(v);
    float lo = v - __bfloat162float(h);
    th[i] = h;
    tl[i] = __float2bfloat16(lo);
}

// ---------------- mma.sync GEMM: C[M,256] = A[M,K] @ Wt^T (+bias) ----------
// Wt stored [256, KP] bf16 hi/lo, K-major, zero padded to KP (mult of 32).
// CTA tile 128x128 (grid.y = col half). 8 warps, warp tile 64x32.
#define KROWB 80                     /* bytes per smem row (32 halves + pad) */
#define ABUF_H 0
#define ABUF_L (128 * KROWB)         /* 10240 */
#define BBUF_H (2 * 128 * KROWB)     /* 20480 */
#define BBUF_L (3 * 128 * KROWB)     /* 30720 */
#define BUFSZ  (4 * 128 * KROWB)     /* 40960 */
#define MM_SMEM (2 * BUFSZ)          /* 81920 */

__global__ void __launch_bounds__(256, 1)
mm_mma_kernel(const float* __restrict__ A,
              const __nv_bfloat16* __restrict__ Bh,
              const __nv_bfloat16* __restrict__ Bl,
              const float* __restrict__ bias,
              float* __restrict__ C, int M, int Kdim, int KP)
{
    extern __shared__ char smem[];
    const int tid = threadIdx.x, wid = tid >> 5, lane = tid & 31;
    const int group = lane >> 2, tig = lane & 3;
    const int rg = wid >> 2, cg = wid & 3;
    const int r0 = blockIdx.x * 128, n0 = blockIdx.y * 128;

    float acc[4][4][4];
#pragma unroll
    for (int mt = 0; mt < 4; mt++)
#pragma unroll
        for (int nt = 0; nt < 4; nt++)
#pragma unroll
            for (int j = 0; j < 4; j++) acc[mt][nt][j] = 0.f;

    const int NCH = KP >> 5;
    const int arow = tid >> 1;
    const int acol0 = (tid & 1) * 16;
    const bool arok = (r0 + arow) < M;
    const float* Abase = A + (size_t)(r0 + arow) * Kdim;

    float apf[16];
    uint4 bpfh[2], bpfl[2];

#define LDG_CHUNK(K0) do {                                                   \
    _Pragma("unroll")                                                        \
    for (int ii = 0; ii < 4; ii++) {                                         \
        int c = (K0) + acol0 + ii * 4;                                       \
        float4 v = make_float4(0.f, 0.f, 0.f, 0.f);                          \
        if (arok) {                                                          \
            if (c + 3 < Kdim) v = *(const float4*)(Abase + c);               \
            else {                                                           \
                if (c     < Kdim) v.x = Abase[c];                            \
                if (c + 1 < Kdim) v.y = Abase[c + 1];                        \
                if (c + 2 < Kdim) v.z = Abase[c + 2];                        \
                if (c + 3 < Kdim) v.w = Abase[c + 3];                        \
            }                                                                \
        }                                                                    \
        apf[ii*4+0] = v.x; apf[ii*4+1] = v.y;                                \
        apf[ii*4+2] = v.z; apf[ii*4+3] = v.w;                                \
    }                                                                        \
    _Pragma("unroll")                                                        \
    for (int q = 0; q < 2; q++) {                                            \
        int idx = tid * 2 + q;                                               \
        int n = idx >> 2, seg = idx & 3;                                     \
        size_t so = (size_t)(n0 + n) * KP + (K0) + seg * 8;                  \
        bpfh[q] = *(const uint4*)(Bh + so);                                  \
        bpfl[q] = *(const uint4*)(Bl + so);                                  \
    }                                                                        \
} while (0)

    LDG_CHUNK(0);

    for (int i = 0; i < NCH; i++) {
        char* buf = smem + (size_t)(i & 1) * BUFSZ;

        // ---- STS (convert A fp32 -> bf16 hi/lo) ----
        {
            uint32_t ph[8], pl[8];
#pragma unroll
            for (int j = 0; j < 8; j++) {
                float vx = apf[2 * j], vy = apf[2 * j + 1];
                float hx = __bfloat162float(__float2bfloat16(vx));
                float hy = __bfloat162float(__float2bfloat16(vy));
                ph[j] = bf2pack(vx, vy);
                pl[j] = bf2pack(vx - hx, vy - hy);
            }
            uint32_t aoff = arow * KROWB + acol0 * 2;
            *(uint4*)(buf + ABUF_H + aoff)      = make_uint4(ph[0], ph[1], ph[2], ph[3]);
            *(uint4*)(buf + ABUF_H + aoff + 16) = make_uint4(ph[4], ph[5], ph[6], ph[7]);
            *(uint4*)(buf + ABUF_L + aoff)      = make_uint4(pl[0], pl[1], pl[2], pl[3]);
            *(uint4*)(buf + ABUF_L + aoff + 16) = make_uint4(pl[4], pl[5], pl[6], pl[7]);
#pragma unroll
            for (int q = 0; q < 2; q++) {
                int idx = tid * 2 + q;
                int n = idx >> 2, seg = idx & 3;
                uint32_t boff = n * KROWB + seg * 16;
                *(uint4*)(buf + BBUF_H + boff) = bpfh[q];
                *(uint4*)(buf + BBUF_L + boff) = bpfl[q];
            }
        }
        __syncthreads();

        if (i + 1 < NCH) LDG_CHUNK((i + 1) << 5);

        // ---- compute: 2 k-steps x (hh, hl, lh) ----
#pragma unroll
        for (int ks = 0; ks < 2; ks++) {
            const uint32_t kb = (uint32_t)(ks * 16 + tig * 2) * 2;
            uint32_t ah[4][4], bhf[4][2], blf[4][2], alf[4][4];
#pragma unroll
            for (int mt = 0; mt < 4; mt++) {
                uint32_t rb = (uint32_t)(rg * 64 + mt * 16 + group) * KROWB;
                ah[mt][0] = *(const uint32_t*)(buf + ABUF_H + rb + kb);
                ah[mt][1] = *(const uint32_t*)(buf + ABUF_H + rb + 8 * KROWB + kb);
                ah[mt][2] = *(const uint32_t*)(buf + ABUF_H + rb + kb + 16);
                ah[mt][3] = *(const uint32_t*)(buf + ABUF_H + rb + 8 * KROWB + kb + 16);
            }
#pragma unroll
            for (int nt = 0; nt < 4; nt++) {
                uint32_t nb = (uint32_t)(cg * 32 + nt * 8 + group) * KROWB;
                bhf[nt][0] = *(const uint32_t*)(buf + BBUF_H + nb + kb);
                bhf[nt][1] = *(const uint32_t*)(buf + BBUF_H + nb + kb + 16);
            }
#pragma unroll
            for (int mt = 0; mt < 4; mt++)
#pragma unroll
                for (int nt = 0; nt < 4; nt++)
                    mma16816(acc[mt][nt], ah[mt], bhf[nt]);
#pragma unroll
            for (int nt = 0; nt < 4; nt++) {
                uint32_t nb = (uint32_t)(cg * 32 + nt * 8 + group) * KROWB;
                blf[nt][0] = *(const uint32_t*)(buf + BBUF_L + nb + kb);
                blf[nt][1] = *(const uint32_t*)(buf + BBUF_L + nb + kb + 16);
            }
#pragma unroll
            for (int mt = 0; mt < 4; mt++)
#pragma unroll
                for (int nt = 0; nt < 4; nt++)
                    mma16816(acc[mt][nt], ah[mt], blf[nt]);
#pragma unroll
            for (int mt = 0; mt < 4; mt++) {
                uint32_t rb = (uint32_t)(rg * 64 + mt * 16 + group) * KROWB;
                alf[mt][0] = *(const uint32_t*)(buf + ABUF_L + rb + kb);
                alf[mt][1] = *(const uint32_t*)(buf + ABUF_L + rb + 8 * KROWB + kb);
                alf[mt][2] = *(const uint32_t*)(buf + ABUF_L + rb + kb + 16);
                alf[mt][3] = *(const uint32_t*)(buf + ABUF_L + rb + 8 * KROWB + kb + 16);
            }
#pragma unroll
            for (int mt = 0; mt < 4; mt++)
#pragma unroll
                for (int nt = 0; nt < 4; nt++)
                    mma16816(acc[mt][nt], alf[mt], bhf[nt]);
        }
    }

    // ---- epilogue ----
#pragma unroll
    for (int nt = 0; nt < 4; nt++) {
        int c = n0 + cg * 32 + nt * 8 + tig * 2;
        float b0v = bias ? __ldg(bias + c) : 0.f;
        float b1v = bias ? __ldg(bias + c + 1) : 0.f;
#pragma unroll
        for (int mt = 0; mt < 4; mt++) {
            int r = r0 + rg * 64 + mt * 16 + group;
            if (r < M)
                *(float2*)(C + (size_t)r * 256 + c) =
                    make_float2(acc[mt][nt][0] + b0v, acc[mt][nt][1] + b1v);
            if (r + 8 < M)
                *(float2*)(C + (size_t)(r + 8) * 256 + c) =
                    make_float2(acc[mt][nt][2] + b0v, acc[mt][nt][3] + b1v);
        }
    }
#undef LDG_CHUNK
}

// ---------------- CSR build ------------------------------------------------
__global__ void deg_init_kernel(int* deg) {
    int i = blockIdx.x * blockDim.x + threadIdx.x;
    if (i < NN) deg[i] = 1;
}
__global__ void deg_count_kernel(const int* __restrict__ ei, int* deg) {
    int i = blockIdx.x * blockDim.x + threadIdx.x;
    if (i < EE) atomicAdd(&deg[ei[EE + i]], 1);
}
__global__ void scan_kernel(const int* __restrict__ deg, int* off, int* pos) {
    __shared__ int sm[1024];
    const int t = threadIdx.x;
    const int base = t * 40;
    int v[40];
    int local = 0;
#pragma unroll
    for (int i = 0; i < 40; i++) {
        int idx = base + i;
        int d = (idx < NN) ? deg[idx] : 0;
        v[i] = local;
        local += d;
    }
    sm[t] = local;
    __syncthreads();
    for (int o = 1; o < 1024; o <<= 1) {
        int add = (t >= o) ? sm[t - o] : 0;
        __syncthreads();
        sm[t] += add;
        __syncthreads();
    }
    int excl = sm[t] - local;
#pragma unroll
    for (int i = 0; i < 40; i++) {
        int idx = base + i;
        if (idx < NN) {
            int o_ = excl + v[i];
            off[idx] = o_;
            pos[idx] = o_;
        }
    }
    if (t == 1023) off[NN] = sm[1023];
}
__global__ void csr_fill_kernel(const int* __restrict__ ei, int* pos, int* csr) {
    int i = blockIdx.x * blockDim.x + threadIdx.x;
    if (i >= ETOT) return;
    int s, d;
    if (i < EE) { s = ei[i]; d = ei[EE + i]; }
    else        { s = d = i - EE; }
    int p = atomicAdd(&pos[d], 1);
    csr[p] = s;
}

// ---------------- attention scores ----------------------------------------
template <int H, int C>
__global__ void scores_kernel(const float* __restrict__ h,
                              const float* __restrict__ asrc,
                              const float* __restrict__ adst,
                              float* __restrict__ ssrc, float* __restrict__ sdst)
{
    int gw = (blockIdx.x * blockDim.x + threadIdx.x) >> 5;
    if (gw >= NN) return;
    int lane = threadIdx.x & 31;

    const float4* hp = (const float4*)(h + gw * 256 + lane * 8);
    float4 v0 = hp[0], v1 = hp[1];
    const float4* ap = (const float4*)(asrc + lane * 8);
    float4 a0 = ap[0], a1 = ap[1];
    const float4* dp = (const float4*)(adst + lane * 8);
    float4 d0 = dp[0], d1 = dp[1];

    float ps = v0.x * a0.x + v0.y * a0.y + v0.z * a0.z + v0.w * a0.w +
               v1.x * a1.x + v1.y * a1.y + v1.z * a1.z + v1.w * a1.w;
    float pd = v0.x * d0.x + v0.y * d0.y + v0.z * d0.z + v0.w * d0.w +
               v1.x * d1.x + v1.y * d1.y + v1.z * d1.z + v1.w * d1.w;

    const int GC = C / 8;
#pragma unroll
    for (int o = 1; o < GC; o <<= 1) {
        ps += __shfl_xor_sync(0xffffffffu, ps, o);
        pd += __shfl_xor_sync(0xffffffffu, pd, o);
    }
    int myh = lane / GC;
    if ((lane & (GC - 1)) == 0) {
        ssrc[gw * H + myh] = ps;
        sdst[gw * H + myh] = pd;
    }
}

// ---------------- GAT aggregation: one warp per destination ---------------
template <int H, int C>
__global__ void agg_kernel(const float* __restrict__ ssrc,
                           const float* __restrict__ sdst,
                           const float* __restrict__ h,
                           const int* __restrict__ off,
                           const int* __restrict__ csr,
                           float* __restrict__ out)
{
    int gw = (blockIdx.x * blockDim.x + threadIdx.x) >> 5;
    if (gw >= NN) return;
    int lane = threadIdx.x & 31;

    int e0 = off[gw];
    int deg = off[gw + 1] - e0;

    const int ES = 32 / H;
    int hh = lane % H;
    int j0 = lane / H;

    float sd = __ldg(&sdst[gw * H + hh]);
    float m = -1e30f;
    for (int j = j0; j < deg; j += ES) {
        int s = __ldg(&csr[e0 + j]);
        float e = __ldg(&ssrc[s * H + hh]) + sd;
        e = e > 0.f ? e : 0.2f * e;
        m = fmaxf(m, e);
    }
#pragma unroll
    for (int o = H; o < 32; o <<= 1) m = fmaxf(m, __shfl_xor_sync(0xffffffffu, m, o));

    float z = 0.f;
    for (int j = j0; j < deg; j += ES) {
        int s = __ldg(&csr[e0 + j]);
        float e = __ldg(&ssrc[s * H + hh]) + sd;
        e = e > 0.f ? e : 0.2f * e;
        z += __expf(e - m);
    }
#pragma unroll
    for (int o = H; o < 32; o <<= 1) z += __shfl_xor_sync(0xffffffffu, z, o);

    const int myh = (lane * 8) / C;
    float my_m  = __shfl_sync(0xffffffffu, m, myh);
    float my_zi = 1.f / __shfl_sync(0xffffffffu, z, myh);
    float my_sd = __ldg(&sdst[gw * H + myh]);

    float acc[8] = {0.f, 0.f, 0.f, 0.f, 0.f, 0.f, 0.f, 0.f};
    for (int j = 0; j < deg; j++) {
        int s = __ldg(&csr[e0 + j]);
        float e = __ldg(&ssrc[s * H + myh]) + my_sd;
        e = e > 0.f ? e : 0.2f * e;
        float a = __expf(e - my_m) * my_zi;
        const float4* hp = (const float4*)(h + s * 256 + lane * 8);
        float4 v0 = __ldg(hp);
        float4 v1 = __ldg(hp + 1);
        acc[0] += a * v0.x; acc[1] += a * v0.y; acc[2] += a * v0.z; acc[3] += a * v0.w;
        acc[4] += a * v1.x; acc[5] += a * v1.y; acc[6] += a * v1.z; acc[7] += a * v1.w;
    }
    float4* op = (float4*)(out + gw * 256 + lane * 8);
    op[0] = make_float4(acc[0], acc[1], acc[2], acc[3]);
    op[1] = make_float4(acc[4], acc[5], acc[6], acc[7]);
}

// ---------------- elu + bias + residual + layernorm (warp per row) --------
__global__ void post_kernel(const float* __restrict__ agg,
                            const float* __restrict__ bias,
                            const float* __restrict__ xin,
                            const float* __restrict__ g,
                            const float* __restrict__ be,
                            float* __restrict__ xout)
{
    int gw = (blockIdx.x * blockDim.x + threadIdx.x) >> 5;
    if (gw >= NN) return;
    int lane = threadIdx.x & 31;
    int base = gw * 256 + lane * 8;

    float4 a0 = *(const float4*)(agg + base);
    float4 a1 = *(const float4*)(agg + base + 4);
    float4 b0 = *(const float4*)(bias + lane * 8);
    float4 b1 = *(const float4*)(bias + lane * 8 + 4);
    float4 x0 = *(const float4*)(xin + base);
    float4 x1 = *(const float4*)(xin + base + 4);

    float av[8] = {a0.x + b0.x, a0.y + b0.y, a0.z + b0.z, a0.w + b0.w,
                   a1.x + b1.x, a1.y + b1.y, a1.z + b1.z, a1.w + b1.w};
    float xv[8] = {x0.x, x0.y, x0.z, x0.w, x1.x, x1.y, x1.z, x1.w};

    float v[8];
    float sum = 0.f, sq = 0.f;
#pragma unroll
    for (int k = 0; k < 8; k++) {
        float t = av[k];
        t = (t > 0.f) ? t : (__expf(t) - 1.f);
        t += xv[k];
        v[k] = t;
        sum += t;
        sq += t * t;
    }
#pragma unroll
    for (int o = 1; o < 32; o <<= 1) {
        sum += __shfl_xor_sync(0xffffffffu, sum, o);
        sq  += __shfl_xor_sync(0xffffffffu, sq, o);
    }
    float mean = sum * (1.f / 256.f);
    float var  = sq * (1.f / 256.f) - mean * mean;
    float rs   = rsqrtf(var + 1e-5f);

    float4 g0 = *(const float4*)(g + lane * 8);
    float4 g1 = *(const float4*)(g + lane * 8 + 4);
    float4 e0 = *(const float4*)(be + lane * 8);
    float4 e1 = *(const float4*)(be + lane * 8 + 4);
    float gv[8] = {g0.x, g0.y, g0.z, g0.w, g1.x, g1.y, g1.z, g1.w};
    float ev[8] = {e0.x, e0.y, e0.z, e0.w, e1.x, e1.y, e1.z, e1.w};

    float o0[8];
#pragma unroll
    for (int k = 0; k < 8; k++) o0[k] = (v[k] - mean) * rs * gv[k] + ev[k];
    *(float4*)(xout + base)     = make_float4(o0[0], o0[1], o0[2], o0[3]);
    *(float4*)(xout + base + 4) = make_float4(o0[4], o0[5], o0[6], o0[7]);
}

// ---------------- pooling --------------------------------------------------
__global__ void pool_init_kernel(float* p2, float* p0, float* cnt) {
    int i = blockIdx.x * blockDim.x + threadIdx.x;
    if (i < BB * DD) { p2[i] = 0.f; p0[i] = 0.f; }
    if (i < BB) cnt[i] = 0.f;
}
__global__ void pool_acc_kernel(const float* __restrict__ x2,
                                const float* __restrict__ x0,
                                const int* __restrict__ batch,
                                float* p2, float* p0, float* cnt)
{
    int r = blockIdx.x;
    int t = threadIdx.x;
    int b = batch[r];
    atomicAdd(&p2[b * 256 + t], x2[r * 256 + t]);
    atomicAdd(&p0[b * 256 + t], x0[r * 256 + t]);
    if (t == 0) atomicAdd(&cnt[b], 1.f);
}

// ---------------- classification head (block per graph) -------------------
__global__ void head_kernel(const float* __restrict__ p2,
                            const float* __restrict__ p0,
                            const float* __restrict__ cnt,
                            const float* __restrict__ Wf,  const float* __restrict__ bf,
                            const float* __restrict__ Wc1, const float* __restrict__ bc1,
                            const float* __restrict__ Wc2, const float* __restrict__ bc2,
                            float* __restrict__ out)
{
    __shared__ float xc[512];
    __shared__ float f[256];
    __shared__ float c1[128];
    __shared__ float lg[20];

    int b = blockIdx.x, t = threadIdx.x;
    float c = fmaxf(cnt[b], 1.f);
    xc[t]       = p2[b * 256 + t] / c;
    xc[256 + t] = p0[b * 256 + t] / c;
    __syncthreads();

    float acc = bf[t];
    for (int i = 0; i < 512; i++) acc += xc[i] * Wf[i * 256 + t];
    f[t] = fmaxf(acc, 0.f);
    __syncthreads();

    if (t < 128) {
        float a = bc1[t];
        for (int i = 0; i < 256; i++) a += f[i] * Wc1[i * 128 + t];
        c1[t] = fmaxf(a, 0.f);
    }
    __syncthreads();

    if (t < 20) {
        float a = bc2[t];
        for (int i = 0; i < 128; i++) a += c1[i] * Wc2[i * 20 + t];
        lg[t] = a;
    }
    __syncthreads();

    if (t < 32) {
        float v = (t < 20) ? lg[t] : -1e30f;
        float m = v;
#pragma unroll
        for (int o = 1; o < 32; o <<= 1) m = fmaxf(m, __shfl_xor_sync(0xffffffffu, m, o));
        float e = (t < 20) ? expf(v - m) : 0.f;
        float s = e;
#pragma unroll
        for (int o = 1; o < 32; o <<= 1) s += __shfl_xor_sync(0xffffffffu, s, o);
        if (t < 20) out[b * 20 + t] = v - m - logf(s);
    }
}

// ---------------- launcher -------------------------------------------------
extern "C" void kernel_launch(void* const* d_in, const int* in_sizes, int n_in,
                              void* d_out, int out_size)
{
    const float* x    = (const float*)d_in[0];
    const int*   ei   = (const int*)  d_in[1];
    const int*   batch= (const int*)  d_in[2];
    const float* W_in = (const float*)d_in[3];
    const float* b_in = (const float*)d_in[4];
    const float* W1   = (const float*)d_in[5];
    const float* as1  = (const float*)d_in[6];
    const float* ad1  = (const float*)d_in[7];
    const float* b1   = (const float*)d_in[8];
    const float* g1   = (const float*)d_in[9];
    const float* be1  = (const float*)d_in[10];
    const float* W2   = (const float*)d_in[11];
    const float* as2  = (const float*)d_in[12];
    const float* ad2  = (const float*)d_in[13];
    const float* b2   = (const float*)d_in[14];
    const float* g2   = (const float*)d_in[15];
    const float* be2  = (const float*)d_in[16];
    const float* Wf   = (const float*)d_in[17];
    const float* bfv  = (const float*)d_in[18];
    const float* Wc1  = (const float*)d_in[19];
    const float* bc1  = (const float*)d_in[20];
    const float* Wc2  = (const float*)d_in[21];
    const float* bc2  = (const float*)d_in[22];
    float* out = (float*)d_out;

    float *x0, *x1, *h, *agg, *ssrc, *sdst, *p2, *p0, *cnt;
    int *deg, *off, *pos, *csr;
    __nv_bfloat16 *wbh, *wbl, *w1h, *w1l, *w2h, *w2l;
    cudaGetSymbolAddress((void**)&x0,  g_x0);
    cudaGetSymbolAddress((void**)&x1,  g_x1);
    cudaGetSymbolAddress((void**)&h,   g_h);
    cudaGetSymbolAddress((void**)&agg, g_agg);
    cudaGetSymbolAddress((void**)&ssrc,g_ssrc);
    cudaGetSymbolAddress((void**)&sdst,g_sdst);
    cudaGetSymbolAddress((void**)&deg, g_deg);
    cudaGetSymbolAddress((void**)&off, g_off);
    cudaGetSymbolAddress((void**)&pos, g_pos);
    cudaGetSymbolAddress((void**)&csr, g_csr);
    cudaGetSymbolAddress((void**)&p2,  g_p2);
    cudaGetSymbolAddress((void**)&p0,  g_p0);
    cudaGetSymbolAddress((void**)&cnt, g_cnt);
    cudaGetSymbolAddress((void**)&wbh, g_wbt_hi);
    cudaGetSymbolAddress((void**)&wbl, g_wbt_lo);
    cudaGetSymbolAddress((void**)&w1h, g_w1t_hi);
    cudaGetSymbolAddress((void**)&w1l, g_w1t_lo);
    cudaGetSymbolAddress((void**)&w2h, g_w2t_hi);
    cudaGetSymbolAddress((void**)&w2l, g_w2t_lo);

    cudaFuncSetAttribute(mm_mma_kernel, cudaFuncAttributeMaxDynamicSharedMemorySize, MM_SMEM);

    const int WARP_BLOCKS = NN / 8;
    const dim3 MMGRID((NN + 127) / 128, 2);   // 313 x 2

    // weight prep (bf16 hi/lo, transposed, padded)
    wprep_kernel<<<(256 * KPBIG + 255) / 256, 256>>>(W_in, wbh, wbl, KBIG, KPBIG);
    wprep_kernel<<<(256 * 256 + 255) / 256, 256>>>(W1, w1h, w1l, 256, 256);
    wprep_kernel<<<(256 * 256 + 255) / 256, 256>>>(W2, w2h, w2l, 256, 256);

    // CSR build
    deg_init_kernel<<<(NN + 255) / 256, 256>>>(deg);
    deg_count_kernel<<<(EE + 255) / 256, 256>>>(ei, deg);
    scan_kernel<<<1, 1024>>>(deg, off, pos);
    csr_fill_kernel<<<(ETOT + 255) / 256, 256>>>(ei, pos, csr);

    // input projection (tensor cores via mma.sync)
    mm_mma_kernel<<<MMGRID, 256, MM_SMEM>>>(x, wbh, wbl, b_in, x0, NN, KBIG, KPBIG);

    // conv1
    mm_mma_kernel<<<MMGRID, 256, MM_SMEM>>>(x0, w1h, w1l, nullptr, h, NN, 256, 256);
    scores_kernel<8, 32><<<WARP_BLOCKS, 256>>>(h, as1, ad1, ssrc, sdst);
    agg_kernel<8, 32><<<WARP_BLOCKS, 256>>>(ssrc, sdst, h, off, csr, agg);
    post_kernel<<<WARP_BLOCKS, 256>>>(agg, b1, x0, g1, be1, x1);

    // conv2
    mm_mma_kernel<<<MMGRID, 256, MM_SMEM>>>(x1, w2h, w2l, nullptr, h, NN, 256, 256);
    scores_kernel<4, 64><<<WARP_BLOCKS, 256>>>(h, as2, ad2, ssrc, sdst);
    agg_kernel<4, 64><<<WARP_BLOCKS, 256>>>(ssrc, sdst, h, off, csr, agg);
    post_kernel<<<WARP_BLOCKS, 256>>>(agg, b2, x1, g2, be2, h);  // h := x2

    // pooling + head
    pool_init_kernel<<<64, 256>>>(p2, p0, cnt);
    pool_acc_kernel<<<NN, 256>>>(h, x0, batch, p2, p0, cnt);
    head_kernel<<<BB, 256>>>(p2, p0, cnt, Wf, bfv, Wc1, bc1, Wc2, bc2, out);
}